// round 9
// baseline (speedup 1.0000x reference)
#include <cuda_runtime.h>
#include <cuda_bf16.h>
#include <stdint.h>

#define BATCH 16
#define CDIM 256
#define HW 4096
#define KC 32                 // k-chunk (bf16 elems per stage)
#define KSPLIT 8
#define KSEG (HW / KSPLIT)    // 512
#define NKCS (KSEG / KC)      // 16 chunks per CTA
#define SSTR 40               // smem row stride in bf16 (80B; conflict-free ldsm)
#define TAU 8.0f

__device__ float g_part[KSPLIT][BATCH * CDIM * CDIM];   // 32 MB partial dist
__device__ int   g_idx[BATCH * CDIM];

// ---------------- helpers ----------------
__device__ __forceinline__ uint32_t bf2(float x, float y) {
    __nv_bfloat162 h = __floats2bfloat162_rn(x, y);
    return *reinterpret_cast<uint32_t*>(&h);
}
__device__ __forceinline__ uint32_t smaddr(const void* p) {
    return (uint32_t)__cvta_generic_to_shared(p);
}
__device__ __forceinline__ void ldsm4(uint32_t a, uint32_t* r) {
    asm volatile("ldmatrix.sync.aligned.m8n8.x4.shared.b16 {%0,%1,%2,%3}, [%4];"
                 : "=r"(r[0]), "=r"(r[1]), "=r"(r[2]), "=r"(r[3]) : "r"(a));
}
__device__ __forceinline__ void mma_bf16(float* d, const uint32_t* a, const uint32_t* b) {
    asm volatile("mma.sync.aligned.m16n8k16.row.col.f32.bf16.bf16.f32 "
                 "{%0,%1,%2,%3}, {%4,%5,%6,%7}, {%8,%9}, {%0,%1,%2,%3};"
                 : "+f"(d[0]), "+f"(d[1]), "+f"(d[2]), "+f"(d[3])
                 : "r"(a[0]), "r"(a[1]), "r"(a[2]), "r"(a[3]), "r"(b[0]), "r"(b[1]));
}

// ---------------------------------------------------------------------------
// 1) partial dist^2 over one k-segment: |y|^2_seg - 2*dot_seg (bf16 hi MMA).
//    CTA: 128(i) x 128(j) x kseg, 1024 threads, 32 warps 8(i)x4(j), wtile 16x32.
//    Loader: 8 lanes/row x 16B = full 128B line; 1 A-float4 + 1 B-float4/thread.
// ---------------------------------------------------------------------------
__global__ void __launch_bounds__(1024) gemm_bf16_kernel(const float* __restrict__ X,
                                                         const float* __restrict__ Y) {
    __shared__ __nv_bfloat16 sA[2][128 * SSTR];
    __shared__ __nv_bfloat16 sB[2][128 * SSTR];
    __shared__ float ynS[128];

    const int b  = blockIdx.z >> 3;
    const int ks = blockIdx.z & 7;
    const int i0 = blockIdx.y * 128;
    const int j0 = blockIdx.x * 128;
    const int t  = threadIdx.x;

    // loader: rb = row (0..127), o = float4-lane within 128B line
    const int o  = t & 7;
    const int rb = t >> 3;
    const float* aRow = X + (size_t)(b * CDIM + i0 + rb) * HW + ks * KSEG + o * 4;
    const float* bRow = Y + (size_t)(b * CDIM + j0 + rb) * HW + ks * KSEG + o * 4;
    const int smoff = rb * SSTR + o * 4;

    float ysq = 0.f;
    float4 va, vb;

    // prologue: chunk 0
    va = *(const float4*)aRow;
    vb = *(const float4*)bRow;
    ysq += vb.x * vb.x + vb.y * vb.y + vb.z * vb.z + vb.w * vb.w;
    *(uint2*)(sA[0] + smoff) = make_uint2(bf2(va.x, va.y), bf2(va.z, va.w));
    *(uint2*)(sB[0] + smoff) = make_uint2(bf2(vb.x, vb.y), bf2(vb.z, vb.w));
    __syncthreads();

    // warp tiling: 32 warps = 8(i) x 4(j); warp tile 16(m) x 32(n)
    const int lane = t & 31;
    const int w    = t >> 5;
    const int i0w  = (w >> 2) * 16;
    const int j0w  = (w & 3) * 32;
    const int arow = i0w + (lane & 15);
    const int acol = (lane >> 4) * 8;
    const int bn   = j0w + (lane & 7) + ((lane >> 4) << 3);
    const int bk   = ((lane >> 3) & 1) * 8;

    float acc[4][4];
#pragma unroll
    for (int n = 0; n < 4; ++n)
#pragma unroll
        for (int e = 0; e < 4; ++e) acc[n][e] = 0.f;

    int p = 0;
    for (int kc = 0; kc < NKCS; ++kc) {
        const bool more = (kc + 1 < NKCS);
        if (more) {
            va = *(const float4*)(aRow + (kc + 1) * KC);
            vb = *(const float4*)(bRow + (kc + 1) * KC);
            ysq += vb.x * vb.x + vb.y * vb.y + vb.z * vb.z + vb.w * vb.w;
        }

#pragma unroll
        for (int s = 0; s < 2; ++s) {   // two k16 steps per chunk
            uint32_t ah[4], bh0[4], bh1[4];
            ldsm4(smaddr(sA[p] + arow * SSTR + s * 16 + acol), ah);
            const int bo = bn * SSTR + s * 16 + bk;
            ldsm4(smaddr(sB[p] + bo), bh0);
            ldsm4(smaddr(sB[p] + bo + 16 * SSTR), bh1);
            mma_bf16(acc[0], ah, bh0);
            mma_bf16(acc[1], ah, bh0 + 2);
            mma_bf16(acc[2], ah, bh1);
            mma_bf16(acc[3], ah, bh1 + 2);
        }

        if (more) {
            const int np = p ^ 1;
            *(uint2*)(sA[np] + smoff) = make_uint2(bf2(va.x, va.y), bf2(va.z, va.w));
            *(uint2*)(sB[np] + smoff) = make_uint2(bf2(vb.x, vb.y), bf2(vb.z, vb.w));
        }
        __syncthreads();
        p ^= 1;
    }

    // partial ynorm: reduce over the 8 lanes sharing a row
    ysq += __shfl_xor_sync(0xffffffffu, ysq, 1);
    ysq += __shfl_xor_sync(0xffffffffu, ysq, 2);
    ysq += __shfl_xor_sync(0xffffffffu, ysq, 4);
    if (o == 0) ynS[rb] = ysq;
    __syncthreads();

    float* gout = g_part[ks];
#pragma unroll
    for (int nb = 0; nb < 4; ++nb) {
        const int jc = j0w + nb * 8 + (lane & 3) * 2;
        float2 yn = *(float2*)&ynS[jc];
        const int grow = b * CDIM + i0 + i0w + (lane >> 2);
        float2 d0, d1;
        d0.x = yn.x - 2.f * acc[nb][0];
        d0.y = yn.y - 2.f * acc[nb][1];
        d1.x = yn.x - 2.f * acc[nb][2];
        d1.y = yn.y - 2.f * acc[nb][3];
        *(float2*)&gout[(size_t)grow * CDIM + j0 + jc] = d0;
        *(float2*)&gout[(size_t)(grow + 8) * CDIM + j0 + jc] = d1;
    }
}

// ---------------------------------------------------------------------------
// 2) argmin (sum of 8 partials) with exact-fp32 rescue. One block per row.
// ---------------------------------------------------------------------------
__global__ void __launch_bounds__(256) rescore_kernel(const float* __restrict__ X,
                                                      const float* __restrict__ Y) {
    const int row = blockIdx.x;           // b*CDIM + i
    const int b   = row >> 8;
    const int t   = threadIdx.x;

    __shared__ float s_red[8];
    __shared__ float s_minv;
    __shared__ int   s_cnt;
    __shared__ int   s_lst[256];

    const size_t off = (size_t)row * CDIM + t;
    float d = 0.f;
#pragma unroll
    for (int k = 0; k < KSPLIT; ++k) d += g_part[k][off];

    float vv = d;
#pragma unroll
    for (int o = 16; o; o >>= 1) vv = fminf(vv, __shfl_down_sync(0xffffffffu, vv, o));
    if ((t & 31) == 0) s_red[t >> 5] = vv;
    __syncthreads();
    if (t == 0) {
        float m = s_red[0];
#pragma unroll
        for (int i = 1; i < 8; ++i) m = fminf(m, s_red[i]);
        s_minv = m;
        s_cnt = 0;
    }
    __syncthreads();

    if (d <= s_minv + TAU) {
        int pos = atomicAdd(&s_cnt, 1);
        s_lst[pos] = t;
    }
    __syncthreads();

    const int n = s_cnt;
    if (n == 1) {
        if (t == 0) g_idx[row] = s_lst[0];
        return;
    }

    const float* xr = X + (size_t)row * HW;
    float bestv = 3.4e38f;
    int   bestj = 0x7fffffff;
    for (int c = 0; c < n; ++c) {
        const int j = s_lst[c];
        const float* yr = Y + (size_t)(b * CDIM + j) * HW;
        float s = 0.f;
#pragma unroll
        for (int q = 0; q < 4; ++q) {
            float4 xv = ((const float4*)xr)[t + q * 256];
            float4 yv = ((const float4*)yr)[t + q * 256];
            float dx = xv.x - yv.x, dy = xv.y - yv.y, dz = xv.z - yv.z, dw = xv.w - yv.w;
            s += dx * dx + dy * dy + dz * dz + dw * dw;
        }
#pragma unroll
        for (int o = 16; o; o >>= 1) s += __shfl_down_sync(0xffffffffu, s, o);
        if ((t & 31) == 0) s_red[t >> 5] = s;
        __syncthreads();
        if (t == 0) {
            float tot = 0.f;
#pragma unroll
            for (int i = 0; i < 8; ++i) tot += s_red[i];
            if (tot < bestv || (tot == bestv && j < bestj)) { bestv = tot; bestj = j; }
        }
        __syncthreads();
    }
    if (t == 0) g_idx[row] = bestj;
}

// ---------------------------------------------------------------------------
// 3) gather: out[b,i,:] = Y[b, g_idx[b,i], :]
// ---------------------------------------------------------------------------
__global__ void __launch_bounds__(256) gather_kernel(const float* __restrict__ Y,
                                                     float* __restrict__ out) {
    int row  = blockIdx.x >> 2;
    int part = blockIdx.x & 3;
    int bb   = row >> 8;
    int src  = g_idx[row];
    const float4* yp = (const float4*)(Y + (size_t)(bb * CDIM + src) * HW);
    float4*       op = (float4*)(out + (size_t)row * HW);
    int e = part * 256 + threadIdx.x;
    op[e] = yp[e];
}

// ---------------------------------------------------------------------------
extern "C" void kernel_launch(void* const* d_in, const int* in_sizes, int n_in,
                              void* d_out, int out_size) {
    const float* x = (const float*)d_in[0];
    const float* y = (const float*)d_in[1];
    float* out = (float*)d_out;

    dim3 g(CDIM / 128, CDIM / 128, BATCH * KSPLIT);   // 2 x 2 x 128 = 512 CTAs
    gemm_bf16_kernel<<<g, 1024>>>(x, y);

    rescore_kernel<<<BATCH * CDIM, 256>>>(x, y);

    gather_kernel<<<BATCH * CDIM * 4, 256>>>(y, out);
}